// round 16
// baseline (speedup 1.0000x reference)
#include <cuda_runtime.h>
#include <math.h>
#include <stdint.h>

// Hybrid causal depthwise conv1d K=24, T=3000, B=16, C=1024.
//   Batches 0-7 : scalar-FFMA path (R12 core: TMA fill, R=12, conflict-free
//                 48B-stride LDS.128) -> fma pipe.
//   Batches 8-15: banded tf32 GEMM via mma.sync (R15 core, NB=8) -> tensor
//                 pipe + L1.
// CTA paths interleaved via bid%3 (ratio 1:2) so both pipes run concurrently;
// DRAM becomes the binding resource.

#define C_DIM 1024
#define T_LEN 3000
#define KSZ 24
#define NTHREADS 256
// scalar path
#define R_OUT 12
#define NACT 250
#define PAD 24
#define ROW_BYTES (T_LEN * 4)
// mma path
#define SEGLEN 384
#define NTILES 24
#define HALO 24
#define ROWF 408
#define RSTRIDE 420              // 420 % 32 == 4 -> B-frag LDS conflict-free
#define MNB 8                    // batches per mma CTA (8..15)
#define PSTRIDE 18
#define PATCHF (16 * PSTRIDE)

// shared layout (float indices), both paths overlap in one buffer
#define SMF_TOTAL 6080
// scalar: S0=0 (3024), S1=3024 (3024), SW=6048 (24), MBAR=6072 (2x u64)
#define SC_S0 0
#define SC_S1 3024
#define SC_SW 6048
#define SC_MB 6072
// mma: XS=0 (8*420=3360), PATCH=3360 (8*288=2304), SW=5664 (24), MBAR=5688
#define MM_XS 0
#define MM_PATCH 3360
#define MM_SW 5664
#define MM_MB 5688

__device__ __forceinline__ uint32_t f2tf32(float f) {
    uint32_t u;
    asm("cvt.rna.tf32.f32 %0, %1;" : "=r"(u) : "f"(f));
    return u;
}

__device__ __forceinline__ void mma_tf32(float* d, const uint32_t* a,
                                         uint32_t b0, uint32_t b1) {
    asm volatile(
        "mma.sync.aligned.m16n8k8.row.col.f32.tf32.tf32.f32 "
        "{%0,%1,%2,%3}, {%4,%5,%6,%7}, {%8,%9}, {%0,%1,%2,%3};"
        : "+f"(d[0]), "+f"(d[1]), "+f"(d[2]), "+f"(d[3])
        : "r"(a[0]), "r"(a[1]), "r"(a[2]), "r"(a[3]), "r"(b0), "r"(b1));
}

__device__ __forceinline__ void mbar_wait(uint32_t mba, uint32_t parity) {
    uint32_t done;
    asm volatile(
        "{\n\t"
        ".reg .pred p;\n\t"
        "mbarrier.try_wait.parity.acquire.cta.shared::cta.b64 p, [%1], %2;\n\t"
        "selp.b32 %0, 1, 0, p;\n\t"
        "}"
        : "=r"(done) : "r"(mba), "r"(parity) : "memory");
    if (!done) {
        asm volatile(
            "{\n\t"
            ".reg .pred P1;\n\t"
            "WAIT_LOOP_%=:\n\t"
            "mbarrier.try_wait.parity.acquire.cta.shared::cta.b64 P1, [%0], %1, 0x989680;\n\t"
            "@P1 bra.uni WAIT_DONE_%=;\n\t"
            "bra.uni WAIT_LOOP_%=;\n\t"
            "WAIT_DONE_%=:\n\t"
            "}"
            :: "r"(mba), "r"(parity) : "memory");
    }
}

__device__ __forceinline__ void tma_cp(uint32_t sdst, const float* src,
                                       uint32_t bytes, uint32_t mba) {
    asm volatile(
        "cp.async.bulk.shared::cluster.global.mbarrier::complete_tx::bytes "
        "[%0], [%1], %2, [%3];"
        :: "r"(sdst), "l"(src), "r"(bytes), "r"(mba) : "memory");
}

__global__ __launch_bounds__(NTHREADS, 6)
void ssm4d_hybrid_kernel(const float* __restrict__ x,
                         const float* __restrict__ alpha,
                         const float* __restrict__ beta,
                         const float* __restrict__ theta,
                         float* __restrict__ y)
{
    __shared__ __align__(16) float smf[SMF_TOTAL];

    const int bid = blockIdx.x;
    const int tid = threadIdx.x;
    const int path = bid % 3;
    const int s    = bid / 3;
    const int CT = C_DIM * T_LEN;

    if (path == 0) {
        // ================= scalar-FFMA path: batches 0-7 =================
        const int c  = s & 1023;
        const int b0 = s >> 10;                 // 0..3; rows b0 and b0+4
        const int row0 = (b0 * C_DIM + c) * T_LEN;
        const int row1 = ((b0 + 4) * C_DIM + c) * T_LEN;

        float* S0 = smf + SC_S0;
        float* S1 = smf + SC_S1;
        float* sw = smf + SC_SW;
        const uint32_t mb0 = (uint32_t)__cvta_generic_to_shared(smf + SC_MB);
        const uint32_t mb1 = mb0 + 8;
        const uint32_t sd0 = (uint32_t)__cvta_generic_to_shared(S0 + PAD);
        const uint32_t sd1 = (uint32_t)__cvta_generic_to_shared(S1 + PAD);

        if (tid == 0) {
            asm volatile("mbarrier.init.shared.b64 [%0], 1;" :: "r"(mb0) : "memory");
            asm volatile("mbarrier.init.shared.b64 [%0], 1;" :: "r"(mb1) : "memory");
        }
        __syncthreads();

        if (tid == 0) {
            asm volatile("mbarrier.arrive.expect_tx.shared.b64 _, [%0], %1;"
                         :: "r"(mb0), "r"((uint32_t)ROW_BYTES) : "memory");
            tma_cp(sd0, x + row0, ROW_BYTES, mb0);
            asm volatile("mbarrier.arrive.expect_tx.shared.b64 _, [%0], %1;"
                         :: "r"(mb1), "r"((uint32_t)ROW_BYTES) : "memory");
            tma_cp(sd1, x + row1, ROW_BYTES, mb1);
        }

        if (tid < PAD / 4) {
            reinterpret_cast<float4*>(S0)[tid] = make_float4(0.f, 0.f, 0.f, 0.f);
            reinterpret_cast<float4*>(S1)[tid] = make_float4(0.f, 0.f, 0.f, 0.f);
        }
        if (tid < KSZ) {
            float a  = alpha[c];
            float la = logf(fmaxf(a, 1e-6f));
            float d  = expf(la * (float)tid);
            float u  = theta[c] * (float)tid;
            float u2 = u * u;
            float ph = 1.0f - 0.5f * u2 + (u2 * u2) * (1.0f / 24.0f);
            sw[tid] = beta[c] * d * ph;
        }
        __syncthreads();

#pragma unroll
        for (int r = 0; r < 2; r++) {
            mbar_wait(r ? mb1 : mb0, 0u);
            if (tid < NACT) {
                const float* Sc = r ? S1 : S0;
                const int rowbase = r ? row1 : row0;

                float X[R_OUT + KSZ];
                const float4* S4 =
                    reinterpret_cast<const float4*>(&Sc[R_OUT * tid]);
#pragma unroll
                for (int j = 0; j < 9; j++) {
                    float4 v = S4[j];
                    X[4 * j + 0] = v.x; X[4 * j + 1] = v.y;
                    X[4 * j + 2] = v.z; X[4 * j + 3] = v.w;
                }

                float acc[R_OUT];
#pragma unroll
                for (int j = 0; j < R_OUT; j++) acc[j] = 0.0f;

                const float4* sw4 = reinterpret_cast<const float4*>(sw);
#pragma unroll
                for (int g = 0; g < KSZ / 4; g++) {
                    float4 wv = sw4[g];
                    const int k0 = 4 * g;
#pragma unroll
                    for (int j = 0; j < R_OUT; j++)
                        acc[j] = fmaf(wv.x, X[j + 1 + k0 + 0], acc[j]);
#pragma unroll
                    for (int j = 0; j < R_OUT; j++)
                        acc[j] = fmaf(wv.y, X[j + 1 + k0 + 1], acc[j]);
#pragma unroll
                    for (int j = 0; j < R_OUT; j++)
                        acc[j] = fmaf(wv.z, X[j + 1 + k0 + 2], acc[j]);
#pragma unroll
                    for (int j = 0; j < R_OUT; j++)
                        acc[j] = fmaf(wv.w, X[j + 1 + k0 + 3], acc[j]);
                }

                float4* yo =
                    reinterpret_cast<float4*>(y + rowbase + R_OUT * tid);
#pragma unroll
                for (int j = 0; j < 3; j++) {
                    float4 o;
                    o.x = acc[4 * j + 0]; o.y = acc[4 * j + 1];
                    o.z = acc[4 * j + 2]; o.w = acc[4 * j + 3];
                    yo[j] = o;
                }
            }
        }
    } else {
        // ================= tf32 mma path: batches 8-15 =================
        const int m   = s * 2 + (path - 1);     // 0..8191
        const int c   = m & 1023;
        const int seg = m >> 10;                // 0..7
        const int seg_base = seg * SEGLEN;
        const int wid  = tid >> 5;
        const int lane = tid & 31;
        const int grp  = lane >> 2;
        const int thr  = lane & 3;

        float* xs = smf + MM_XS;                // [8][RSTRIDE] raw floats
        float* sw = smf + MM_SW;
        float* patch = smf + MM_PATCH + wid * PATCHF;
        const uint32_t mba = (uint32_t)__cvta_generic_to_shared(smf + MM_MB);

        const int copy_start = (seg_base - HALO < 0) ? 0 : seg_base - HALO;
        const int copy_end   = (seg_base + SEGLEN > T_LEN) ? T_LEN
                                                           : seg_base + SEGLEN;
        const int dst_off    = copy_start - (seg_base - HALO);
        const int len_f      = copy_end - copy_start;
        const int filled_end = dst_off + len_f;

        if (tid == 0) {
            asm volatile("mbarrier.init.shared.b64 [%0], 1;" :: "r"(mba) : "memory");
            asm volatile("mbarrier.arrive.expect_tx.shared.b64 _, [%0], %1;"
                         :: "r"(mba), "r"((uint32_t)(MNB * len_f * 4)) : "memory");
        }
        if (tid < MNB) {
            float4* row4 = reinterpret_cast<float4*>(xs + tid * RSTRIDE);
            for (int v = 0; v < dst_off / 4; v++)
                row4[v] = make_float4(0.f, 0.f, 0.f, 0.f);
            for (int v = filled_end / 4; v < ROWF / 4; v++)
                row4[v] = make_float4(0.f, 0.f, 0.f, 0.f);
        }
        if (tid < KSZ) {
            float a  = alpha[c];
            float la = logf(fmaxf(a, 1e-6f));
            float d  = expf(la * (float)tid);
            float u  = theta[c] * (float)tid;
            float u2 = u * u;
            float ph = 1.0f - 0.5f * u2 + (u2 * u2) * (1.0f / 24.0f);
            sw[tid] = __uint_as_float(f2tf32(beta[c] * d * ph));
        }
        __syncthreads();   // mbar init + expect_tx + zeros + weights visible

        if (tid < MNB) {
            const float* src = x + (8 + tid) * CT + c * T_LEN + copy_start;
            const uint32_t sdst = (uint32_t)__cvta_generic_to_shared(
                xs + tid * RSTRIDE + dst_off);
            tma_cp(sdst, src, (uint32_t)(len_f * 4), mba);
        }

        // A fragments (tile-invariant band of weights)
        uint32_t afr[5][4];
#pragma unroll
        for (int cc = 0; cc < 5; cc++) {
            int k0 = cc * 8 + thr;
            int j;
            j = k0 - grp - 1;
            afr[cc][0] = (j >= 0 && j < KSZ) ? __float_as_uint(sw[j]) : 0u;
            j = k0 - (grp + 8) - 1;
            afr[cc][1] = (j >= 0 && j < KSZ) ? __float_as_uint(sw[j]) : 0u;
            j = (k0 + 4) - grp - 1;
            afr[cc][2] = (j >= 0 && j < KSZ) ? __float_as_uint(sw[j]) : 0u;
            j = (k0 + 4) - (grp + 8) - 1;
            afr[cc][3] = (j >= 0 && j < KSZ) ? __float_as_uint(sw[j]) : 0u;
        }

        mbar_wait(mba, 0u);

        const float* xr0 = xs + grp * RSTRIDE;   // batch 8+grp

#pragma unroll
        for (int tile = wid; tile < NTILES; tile += 8) {
            const int base = tile * 16;
            const int t0g  = seg_base + tile * 16;

            float acc[4] = {0.f, 0.f, 0.f, 0.f};
#pragma unroll
            for (int cc = 0; cc < 5; cc++) {
                const int kb = base + cc * 8 + thr;
                uint32_t b0 = f2tf32(xr0[kb]);
                uint32_t b1 = f2tf32(xr0[kb + 4]);
                mma_tf32(acc, afr[cc], b0, b1);
            }

            // transpose via warp-private patch: D rows m=grp,grp+8 (t),
            // cols 2thr,2thr+1 (n)
            *reinterpret_cast<float2*>(&patch[grp * PSTRIDE + 2 * thr]) =
                make_float2(acc[0], acc[1]);
            *reinterpret_cast<float2*>(&patch[(grp + 8) * PSTRIDE + 2 * thr]) =
                make_float2(acc[2], acc[3]);
            __syncwarp();

            {
                int n  = lane >> 2;            // 0..7 -> batch 8+n
                int t4 = lane & 3;
                int tg = t0g + 4 * t4;
                if (tg < T_LEN) {
                    float4 o;
                    o.x = patch[(4 * t4 + 0) * PSTRIDE + n];
                    o.y = patch[(4 * t4 + 1) * PSTRIDE + n];
                    o.z = patch[(4 * t4 + 2) * PSTRIDE + n];
                    o.w = patch[(4 * t4 + 3) * PSTRIDE + n];
                    *reinterpret_cast<float4*>(
                        y + (8 + n) * CT + c * T_LEN + tg) = o;
                }
            }
            __syncwarp();
        }
    }
}

extern "C" void kernel_launch(void* const* d_in, const int* in_sizes, int n_in,
                              void* d_out, int out_size)
{
    const float* x     = (const float*)d_in[0];
    const float* alpha = (const float*)d_in[1];
    const float* beta  = (const float*)d_in[2];
    const float* theta = (const float*)d_in[3];
    float* y = (float*)d_out;

    // 4096 scalar CTAs (bid%3==0) + 8192 mma CTAs (bid%3!=0), interleaved
    ssm4d_hybrid_kernel<<<12288, NTHREADS>>>(x, alpha, beta, theta, y);
}